// round 1
// baseline (speedup 1.0000x reference)
#include <cuda_runtime.h>

#define ALPHA 0.5f
#define BATA  0.01f
#define LAMDA 0.01f
#define GAMA  0.01f
#define DIM   64

__global__ void zero_out_kernel(float* out) {
    if (threadIdx.x == 0) out[0] = 0.0f;
}

__global__ __launch_bounds__(256, 4)
void fism_kernel(const float* __restrict__ bu,
                 const float* __restrict__ bi,
                 const float* __restrict__ qi,
                 const float* __restrict__ pu,
                 const float* __restrict__ uin,
                 const int*   __restrict__ users,
                 const int*   __restrict__ pos_items,
                 const int*   __restrict__ neg_items,
                 const int*   __restrict__ hist_items,
                 const int*   __restrict__ hist_segids,
                 int total, int n_neg,
                 float* __restrict__ out)
{
    __shared__ float s_ue[DIM];
    __shared__ float s_loss;
    __shared__ int   s_start, s_end;

    const int b   = blockIdx.x;
    const int tid = threadIdx.x;

    if (tid == 0) {
        // lower_bound(b)
        int lo = 0, hi = total;
        while (lo < hi) { int mid = (lo + hi) >> 1; if (hist_segids[mid] <  b) lo = mid + 1; else hi = mid; }
        s_start = lo;
        // upper_bound(b)
        hi = total;
        while (lo < hi) { int mid = (lo + hi) >> 1; if (hist_segids[mid] <= b) lo = mid + 1; else hi = mid; }
        s_end  = lo;
        s_loss = 0.0f;
    }
    if (tid < DIM) s_ue[tid] = 0.0f;
    __syncthreads();

    // ---- Phase A: ragged segment-sum of pu rows (EmbeddingBag-sum) ----
    const int d = tid & (DIM - 1);   // dim lane 0..63
    const int g = tid >> 6;          // group 0..3
    const int seg_start = s_start, seg_end = s_end;
    float acc = 0.0f;
    for (int i = seg_start + g; i < seg_end; i += 4) {
        int it = __ldg(&hist_items[i]);
        acc += __ldg(&pu[(long)it * DIM + d]);
    }
    atomicAdd(&s_ue[d], acc);
    __syncthreads();

    // BATA * ||user_embed||^2  (one contribution per dim)
    if (tid < DIM) {
        float v = s_ue[tid];
        atomicAdd(&s_loss, BATA * v * v);
    }

    // ---- Phase B: 51 scored items (j=0 -> positive, j>=1 -> negative) ----
    const float t   = rsqrtf(uin[b]);          // uin^(-ALPHA), ALPHA = 0.5
    const float b_u = bu[users[b]];
    const int lane = tid & 31;
    const int w    = tid >> 5;                 // warp 0..7
    const float ue0 = s_ue[lane];
    const float ue1 = s_ue[lane + 32];

    float wloss = 0.0f;
    const int n_items = n_neg + 1;
    for (int j = w; j < n_items; j += 8) {
        int row = (j == 0) ? __ldg(&pos_items[b])
                           : __ldg(&neg_items[(long)b * n_neg + (j - 1)]);
        float q0 = __ldg(&qi[(long)row * DIM + lane]);
        float q1 = __ldg(&qi[(long)row * DIM + 32 + lane]);
        float part = ue0 * q0 + ue1 * q1;
        float sq   = (j == 0) ? (q0 * q0 + q1 * q1) : 0.0f;
        #pragma unroll
        for (int off = 16; off; off >>= 1) {
            part += __shfl_down_sync(0xffffffffu, part, off);
            sq   += __shfl_down_sync(0xffffffffu, sq,   off);
        }
        if (lane == 0) {
            float bir = __ldg(&bi[row]);
            float x = t * part + bir + b_u;
            float s = 1.0f / (1.0f + __expf(-x));
            if (j == 0) {
                float e = 1.0f - s;
                wloss += e * e + BATA * sq + LAMDA * bir * bir;
            } else {
                wloss += s * s;
            }
        }
    }
    if (lane == 0) atomicAdd(&s_loss, wloss);

    if (tid == 0) {
        // LAMDA * GAMA * bu[user]^2
        atomicAdd(&s_loss, LAMDA * GAMA * b_u * b_u);
    }
    __syncthreads();

    if (tid == 0) atomicAdd(out, s_loss);
}

extern "C" void kernel_launch(void* const* d_in, const int* in_sizes, int n_in,
                              void* d_out, int out_size)
{
    const float* bu          = (const float*)d_in[0];
    const float* bi          = (const float*)d_in[1];
    const float* qi          = (const float*)d_in[2];
    const float* pu          = (const float*)d_in[3];
    const float* uin         = (const float*)d_in[4];
    const int*   users       = (const int*)  d_in[5];
    const int*   pos_items   = (const int*)  d_in[6];
    const int*   neg_items   = (const int*)  d_in[7];
    const int*   hist_items  = (const int*)  d_in[8];
    const int*   hist_segids = (const int*)  d_in[9];

    const int B     = in_sizes[5];              // 4096 users in batch
    const int total = in_sizes[8];              // 204800 history items
    const int n_neg = in_sizes[7] / B;          // 50 negatives/user

    float* out = (float*)d_out;

    zero_out_kernel<<<1, 32>>>(out);
    fism_kernel<<<B, 256>>>(bu, bi, qi, pu, uin, users, pos_items, neg_items,
                            hist_items, hist_segids, total, n_neg, out);
}

// round 2
// speedup vs baseline: 2.6916x; 2.6916x over previous
#include <cuda_runtime.h>

#define ALPHA 0.5f
#define BATA  0.01f
#define LAMDA 0.01f
#define GAMA  0.01f
#define DIM   64
#define BMAX  8192

__device__ int g_starts[BMAX + 1];

__global__ void zero_out_kernel(float* out) {
    if (threadIdx.x == 0) out[0] = 0.0f;
}

// starts[b] = first index i with segids[i] >= b  (segids sorted ascending).
// Segment b occupies [starts[b], starts[b+1]).
__global__ void bounds_kernel(const int* __restrict__ segids, int total, int B,
                              int* __restrict__ starts) {
    int i = blockIdx.x * blockDim.x + threadIdx.x;
    if (i >= total) return;
    int cur  = segids[i];
    int prev = (i == 0) ? -1 : segids[i - 1];
    for (int s = prev + 1; s <= cur; ++s) starts[s] = i;
    if (i == total - 1) {
        for (int s = cur + 1; s <= B; ++s) starts[s] = total;
    }
}

__global__ __launch_bounds__(256)
void fism_kernel(const float* __restrict__ bu,
                 const float* __restrict__ bi,
                 const float* __restrict__ qi,
                 const float* __restrict__ pu,
                 const float* __restrict__ uin,
                 const int*   __restrict__ users,
                 const int*   __restrict__ pos_items,
                 const int*   __restrict__ neg_items,
                 const int*   __restrict__ hist_items,
                 int n_neg,
                 float* __restrict__ out)
{
    __shared__ float4 s_part[16][16];   // [row-group r][float4 lane]
    __shared__ float  s_ue[DIM];
    __shared__ float  s_loss;

    const int b   = blockIdx.x;
    const int tid = threadIdx.x;

    if (tid == 0) s_loss = 0.0f;

    const int start = g_starts[b];
    const int end   = g_starts[b + 1];

    // ---- Phase A: ragged segment-sum of pu rows, float4, 16 rows in flight ----
    const int f4 = tid & 15;            // float4 index within a 64-float row
    const int r  = tid >> 4;            // row group 0..15
    const float4* __restrict__ pu4 = (const float4*)pu;

    float4 acc = make_float4(0.f, 0.f, 0.f, 0.f);
    #pragma unroll 2
    for (int i = start + r; i < end; i += 16) {
        int it = __ldg(&hist_items[i]);
        float4 v = __ldg(&pu4[it * 16 + f4]);
        acc.x += v.x; acc.y += v.y; acc.z += v.z; acc.w += v.w;
    }
    s_part[r][f4] = acc;
    __syncthreads();

    // Reduce 16 partials per float4 lane; also BATA*||ue||^2
    if (tid < 16) {
        float4 t = s_part[0][tid];
        #pragma unroll
        for (int rr = 1; rr < 16; rr++) {
            float4 p = s_part[rr][tid];
            t.x += p.x; t.y += p.y; t.z += p.z; t.w += p.w;
        }
        ((float4*)s_ue)[tid] = t;
        float sq = t.x * t.x + t.y * t.y + t.z * t.z + t.w * t.w;
        #pragma unroll
        for (int off = 8; off; off >>= 1)
            sq += __shfl_down_sync(0x0000ffffu, sq, off, 16);
        if (tid == 0) atomicAdd(&s_loss, BATA * sq);
    }
    __syncthreads();

    // ---- Phase B: score 51 items (j=0 positive), 2 items per warp per round ----
    const float tp   = rsqrtf(uin[b]);          // uin^(-0.5)
    const float b_u  = __ldg(&bu[users[b]]);
    const int lane = tid & 31;
    const int w    = tid >> 5;                  // warp 0..7
    const int half = lane >> 4;                 // 0/1: which item this half-warp scores
    const int fl   = lane & 15;                 // float4 lane within half-warp

    const float4 ue4 = ((const float4*)s_ue)[fl];
    const float4* __restrict__ qi4 = (const float4*)qi;

    const int n_items = n_neg + 1;
    const int rounds  = (n_items + 15) >> 4;    // 16 items scored per round (8 warps x 2)

    float wloss = 0.0f;
    for (int rd = 0; rd < rounds; rd++) {
        int j = (w << 1) + half + (rd << 4);
        bool valid = (j < n_items);
        float part = 0.0f, sq = 0.0f;
        int row = 0;
        if (valid) {
            row = (j == 0) ? __ldg(&pos_items[b])
                           : __ldg(&neg_items[b * n_neg + (j - 1)]);
            float4 q = __ldg(&qi4[row * 16 + fl]);
            part = ue4.x * q.x + ue4.y * q.y + ue4.z * q.z + ue4.w * q.w;
            if (j == 0) sq = q.x * q.x + q.y * q.y + q.z * q.z + q.w * q.w;
        }
        #pragma unroll
        for (int off = 8; off; off >>= 1) {
            part += __shfl_down_sync(0xffffffffu, part, off, 16);
            sq   += __shfl_down_sync(0xffffffffu, sq,   off, 16);
        }
        if (valid && fl == 0) {
            float bir = __ldg(&bi[row]);
            float x = tp * part + bir + b_u;
            float s = 1.0f / (1.0f + __expf(-x));
            if (j == 0) {
                float e = 1.0f - s;
                wloss += e * e + BATA * sq + LAMDA * bir * bir;
            } else {
                wloss += s * s;
            }
        }
    }
    // merge the two half-warp accumulators (lanes 0 and 16), one shared atomic per warp
    wloss += __shfl_down_sync(0xffffffffu, wloss, 16);
    if (lane == 0) atomicAdd(&s_loss, wloss);

    if (tid == 0) atomicAdd(&s_loss, LAMDA * GAMA * b_u * b_u);
    __syncthreads();

    if (tid == 0) atomicAdd(out, s_loss);
}

extern "C" void kernel_launch(void* const* d_in, const int* in_sizes, int n_in,
                              void* d_out, int out_size)
{
    const float* bu          = (const float*)d_in[0];
    const float* bi          = (const float*)d_in[1];
    const float* qi          = (const float*)d_in[2];
    const float* pu          = (const float*)d_in[3];
    const float* uin         = (const float*)d_in[4];
    const int*   users       = (const int*)  d_in[5];
    const int*   pos_items   = (const int*)  d_in[6];
    const int*   neg_items   = (const int*)  d_in[7];
    const int*   hist_items  = (const int*)  d_in[8];
    const int*   hist_segids = (const int*)  d_in[9];

    const int B     = in_sizes[5];
    const int total = in_sizes[8];
    const int n_neg = in_sizes[7] / B;

    float* out = (float*)d_out;

    int* starts;
    cudaGetSymbolAddress((void**)&starts, g_starts);

    zero_out_kernel<<<1, 32>>>(out);
    bounds_kernel<<<(total + 255) / 256, 256>>>(hist_segids, total, B, starts);
    fism_kernel<<<B, 256>>>(bu, bi, qi, pu, uin, users, pos_items, neg_items,
                            hist_items, n_neg, out);
}

// round 3
// speedup vs baseline: 2.9425x; 1.0932x over previous
#include <cuda_runtime.h>

#define ALPHA 0.5f
#define BATA  0.01f
#define LAMDA 0.01f
#define GAMA  0.01f
#define DIM   64
#define BMAX  8192
#define CHUNK 512

__device__ int g_starts[BMAX + 1];

// starts[b] = first index i with segids[i] >= b; also zeroes out[0].
__global__ void bounds_kernel(const int* __restrict__ segids, int total, int B,
                              int* __restrict__ starts, float* __restrict__ out) {
    int i = blockIdx.x * blockDim.x + threadIdx.x;
    if (i == 0) out[0] = 0.0f;
    if (i < total) {
        int cur  = segids[i];
        int prev = (i == 0) ? -1 : segids[i - 1];
        for (int s = prev + 1; s <= cur; ++s) starts[s] = i;
        if (i == total - 1)
            for (int s = cur + 1; s <= B; ++s) starts[s] = total;
    }
    cudaTriggerProgrammaticLaunchCompletion();
}

__global__ __launch_bounds__(256)
void fism_kernel(const float* __restrict__ bu,
                 const float* __restrict__ bi,
                 const float* __restrict__ qi,
                 const float* __restrict__ pu,
                 const float* __restrict__ uin,
                 const int*   __restrict__ users,
                 const int*   __restrict__ pos_items,
                 const int*   __restrict__ neg_items,
                 int n_neg,
                 const int*   __restrict__ hist_items,
                 float* __restrict__ out)
{
    __shared__ int    s_idx[CHUNK];
    __shared__ int    s_items[64];
    __shared__ float  s_bi[64];
    __shared__ float4 s_part[16][16];
    __shared__ float  s_ue[DIM];
    __shared__ float  s_loss, s_tp, s_bu;

    cudaGridDependencySynchronize();   // wait for bounds_kernel's g_starts/out

    const int b   = blockIdx.x;
    const int tid = threadIdx.x;
    const int n_items = n_neg + 1;     // <= 64 assumed

    if (tid == 0) s_loss = 0.0f;
    if (tid == 32) {
        s_tp = rsqrtf(__ldg(&uin[b]));           // uin^(-0.5)
        s_bu = __ldg(&bu[__ldg(&users[b])]);
    }
    // Preload scored item ids + their biases (overlaps with phase A staging)
    if (tid < n_items) {
        int row = (tid == 0) ? __ldg(&pos_items[b])
                             : __ldg(&neg_items[b * n_neg + tid - 1]);
        s_items[tid] = row;
        s_bi[tid]    = __ldg(&bi[row]);
    }

    const int start = g_starts[b];
    const int end   = g_starts[b + 1];

    // ---- Phase A: segment-sum of pu rows; indices staged through SMEM ----
    const int f4 = tid & 15;           // float4 lane within 64-float row
    const int r  = tid >> 4;           // row group 0..15
    const float4* __restrict__ pu4 = (const float4*)pu;

    float4 acc = make_float4(0.f, 0.f, 0.f, 0.f);
    for (int base = start; base < end; base += CHUNK) {
        int chunk = min(end - base, CHUNK);
        for (int i = tid; i < chunk; i += 256)
            s_idx[i] = __ldg(&hist_items[base + i]);
        __syncthreads();
        #pragma unroll 2
        for (int i = r; i < chunk; i += 16) {
            float4 v = __ldg(&pu4[s_idx[i] * 16 + f4]);
            acc.x += v.x; acc.y += v.y; acc.z += v.z; acc.w += v.w;
        }
        __syncthreads();
    }
    s_part[r][f4] = acc;
    __syncthreads();

    // Reduce 16 partials per float4 lane; also BATA*||ue||^2
    if (tid < 16) {
        float4 t = s_part[0][tid];
        #pragma unroll
        for (int rr = 1; rr < 16; rr++) {
            float4 p = s_part[rr][tid];
            t.x += p.x; t.y += p.y; t.z += p.z; t.w += p.w;
        }
        ((float4*)s_ue)[tid] = t;
        float sq = t.x * t.x + t.y * t.y + t.z * t.z + t.w * t.w;
        #pragma unroll
        for (int off = 8; off; off >>= 1)
            sq += __shfl_down_sync(0x0000ffffu, sq, off, 16);
        if (tid == 0) atomicAdd(&s_loss, BATA * sq);
    }
    __syncthreads();

    // ---- Phase B: 51 items, 4 per half-warp, batched loads ----
    const float tp  = s_tp;
    const float b_u = s_bu;
    const int lane = tid & 31;
    const int w    = tid >> 5;
    const int half = lane >> 4;
    const int fl   = lane & 15;
    const int hw   = (w << 1) + half;  // half-warp id 0..15

    const float4 ue4 = ((const float4*)s_ue)[fl];
    const float4* __restrict__ qi4 = (const float4*)qi;

    float part[4];
    bool  valid[4];
    float possq = 0.0f;

    #pragma unroll
    for (int k = 0; k < 4; k++) {
        int j = hw + (k << 4);
        valid[k] = (j < n_items);
        part[k] = 0.0f;
        if (valid[k]) {
            int row = s_items[j];
            float4 q = __ldg(&qi4[row * 16 + fl]);
            part[k] = ue4.x * q.x + ue4.y * q.y + ue4.z * q.z + ue4.w * q.w;
            if (j == 0) possq = q.x * q.x + q.y * q.y + q.z * q.z + q.w * q.w;
        }
    }
    #pragma unroll
    for (int off = 8; off; off >>= 1) {
        part[0] += __shfl_down_sync(0xffffffffu, part[0], off, 16);
        part[1] += __shfl_down_sync(0xffffffffu, part[1], off, 16);
        part[2] += __shfl_down_sync(0xffffffffu, part[2], off, 16);
        part[3] += __shfl_down_sync(0xffffffffu, part[3], off, 16);
        possq   += __shfl_down_sync(0xffffffffu, possq,   off, 16);
    }

    float wloss = 0.0f;
    if (fl == 0) {
        #pragma unroll
        for (int k = 0; k < 4; k++) {
            int j = hw + (k << 4);
            if (valid[k]) {
                float bir = s_bi[j];
                float x = tp * part[k] + bir + b_u;
                float s = 1.0f / (1.0f + __expf(-x));
                if (j == 0) {
                    float e = 1.0f - s;
                    wloss += e * e + BATA * possq + LAMDA * bir * bir;
                } else {
                    wloss += s * s;
                }
            }
        }
    }
    wloss += __shfl_down_sync(0xffffffffu, wloss, 16);
    if (lane == 0) atomicAdd(&s_loss, wloss);

    if (tid == 0) atomicAdd(&s_loss, LAMDA * GAMA * b_u * b_u);
    __syncthreads();

    if (tid == 0) atomicAdd(out, s_loss);
}

extern "C" void kernel_launch(void* const* d_in, const int* in_sizes, int n_in,
                              void* d_out, int out_size)
{
    const float* bu          = (const float*)d_in[0];
    const float* bi          = (const float*)d_in[1];
    const float* qi          = (const float*)d_in[2];
    const float* pu          = (const float*)d_in[3];
    const float* uin         = (const float*)d_in[4];
    const int*   users       = (const int*)  d_in[5];
    const int*   pos_items   = (const int*)  d_in[6];
    const int*   neg_items   = (const int*)  d_in[7];
    const int*   hist_items  = (const int*)  d_in[8];
    const int*   hist_segids = (const int*)  d_in[9];

    const int B     = in_sizes[5];
    const int total = in_sizes[8];
    const int n_neg = in_sizes[7] / B;

    float* out = (float*)d_out;

    int* starts;
    cudaGetSymbolAddress((void**)&starts, g_starts);

    bounds_kernel<<<(total + 255) / 256, 256>>>(hist_segids, total, B, starts, out);

    // Programmatic dependent launch: fism may launch while bounds drains;
    // cudaGridDependencySynchronize() inside fism guards g_starts/out visibility.
    cudaLaunchConfig_t cfg = {};
    cfg.gridDim  = dim3(B);
    cfg.blockDim = dim3(256);
    cfg.stream   = 0;
    cudaLaunchAttribute attr[1];
    attr[0].id = cudaLaunchAttributeProgrammaticStreamSerialization;
    attr[0].val.programmaticStreamSerializationAllowed = 1;
    cfg.attrs    = attr;
    cfg.numAttrs = 1;
    cudaLaunchKernelEx(&cfg, fism_kernel, bu, bi, qi, pu, uin, users,
                       pos_items, neg_items, n_neg, hist_items, out);
}

// round 4
// speedup vs baseline: 3.2000x; 1.0875x over previous
#include <cuda_runtime.h>

#define ALPHA 0.5f
#define BATA  0.01f
#define LAMDA 0.01f
#define GAMA  0.01f
#define DIM   64
#define BMAX  8192
#define CHUNK 512

__device__ int g_starts[BMAX + 1];

// starts[b] = first index i with segids[i] >= b; also zeroes out[0].
__global__ void bounds_kernel(const int* __restrict__ segids, int total, int B,
                              int* __restrict__ starts, float* __restrict__ out) {
    int i = blockIdx.x * blockDim.x + threadIdx.x;
    if (i == 0) out[0] = 0.0f;
    if (i < total) {
        int cur  = segids[i];
        int prev = (i == 0) ? -1 : segids[i - 1];
        for (int s = prev + 1; s <= cur; ++s) starts[s] = i;
        if (i == total - 1)
            for (int s = cur + 1; s <= B; ++s) starts[s] = total;
    }
    cudaTriggerProgrammaticLaunchCompletion();
}

__global__ __launch_bounds__(256)
void fism_kernel(const float* __restrict__ bu,
                 const float* __restrict__ bi,
                 const float* __restrict__ qi,
                 const float* __restrict__ pu,
                 const float* __restrict__ uin,
                 const int*   __restrict__ users,
                 const int*   __restrict__ pos_items,
                 const int*   __restrict__ neg_items,
                 int n_neg,
                 const int*   __restrict__ hist_items,
                 float* __restrict__ out)
{
    __shared__ int    s_idx[CHUNK];
    __shared__ int    s_items[64];
    __shared__ float  s_bi[64];
    __shared__ float4 s_part[16][16];
    __shared__ float  s_ue[DIM];
    __shared__ float  s_loss, s_tp, s_bu;

    const int b   = blockIdx.x;
    const int tid = threadIdx.x;
    const int n_items = n_neg + 1;     // <= 64 assumed

    // ---- Everything here is independent of bounds_kernel: overlap PDL wait ----
    if (tid == 0) s_loss = 0.0f;
    if (tid == 32) {
        s_tp = rsqrtf(uin[b]);                   // uin^(-0.5)
        s_bu = bu[users[b]];
    }
    if (tid < n_items) {
        int row = (tid == 0) ? pos_items[b]
                             : neg_items[b * n_neg + tid - 1];
        s_items[tid] = row;
        s_bi[tid]    = bi[row];
    }

    cudaGridDependencySynchronize();   // g_starts (and out-zeroing) now visible

    const int start = g_starts[b];
    const int end   = g_starts[b + 1];

    // ---- Phase A: segment-sum of pu rows; 4-deep batched loads per group ----
    const int f4 = tid & 15;           // float4 lane within 64-float row
    const int r  = tid >> 4;           // row group 0..15
    const float4* __restrict__ pu4 = (const float4*)pu;

    float4 acc = make_float4(0.f, 0.f, 0.f, 0.f);
    for (int base = start; base < end; base += CHUNK) {
        int chunk = min(end - base, CHUNK);
        for (int i = tid; i < chunk; i += 256)
            s_idx[i] = hist_items[base + i];
        __syncthreads();
        for (int i = r; i < chunk; i += 64) {
            // rows i, i+16, i+32, i+48 — one batched latency exposure
            float4 v0 = __ldg(&pu4[s_idx[i] * 16 + f4]);
            float4 v1 = make_float4(0.f, 0.f, 0.f, 0.f);
            float4 v2 = v1, v3 = v1;
            if (i + 16 < chunk) v1 = __ldg(&pu4[s_idx[i + 16] * 16 + f4]);
            if (i + 32 < chunk) v2 = __ldg(&pu4[s_idx[i + 32] * 16 + f4]);
            if (i + 48 < chunk) v3 = __ldg(&pu4[s_idx[i + 48] * 16 + f4]);
            acc.x += v0.x + v1.x + v2.x + v3.x;
            acc.y += v0.y + v1.y + v2.y + v3.y;
            acc.z += v0.z + v1.z + v2.z + v3.z;
            acc.w += v0.w + v1.w + v2.w + v3.w;
        }
        if (base + CHUNK < end) __syncthreads();   // s_idx reused next chunk
    }
    s_part[r][f4] = acc;
    __syncthreads();

    // Reduce 16 partials per float4 lane; also BATA*||ue||^2
    if (tid < 16) {
        float4 t = s_part[0][tid];
        #pragma unroll
        for (int rr = 1; rr < 16; rr++) {
            float4 p = s_part[rr][tid];
            t.x += p.x; t.y += p.y; t.z += p.z; t.w += p.w;
        }
        ((float4*)s_ue)[tid] = t;
        float sq = t.x * t.x + t.y * t.y + t.z * t.z + t.w * t.w;
        #pragma unroll
        for (int off = 8; off; off >>= 1)
            sq += __shfl_down_sync(0x0000ffffu, sq, off, 16);
        if (tid == 0) atomicAdd(&s_loss, BATA * sq);
    }
    __syncthreads();

    // ---- Phase B: 51 items, 4 per half-warp, batched loads ----
    const float tp  = s_tp;
    const float b_u = s_bu;
    const int lane = tid & 31;
    const int w    = tid >> 5;
    const int half = lane >> 4;
    const int fl   = lane & 15;
    const int hw   = (w << 1) + half;  // half-warp id 0..15

    const float4 ue4 = ((const float4*)s_ue)[fl];
    const float4* __restrict__ qi4 = (const float4*)qi;

    float part[4];
    bool  valid[4];
    float possq = 0.0f;

    #pragma unroll
    for (int k = 0; k < 4; k++) {
        int j = hw + (k << 4);
        valid[k] = (j < n_items);
        part[k] = 0.0f;
        if (valid[k]) {
            int row = s_items[j];
            float4 q = __ldg(&qi4[row * 16 + fl]);
            part[k] = ue4.x * q.x + ue4.y * q.y + ue4.z * q.z + ue4.w * q.w;
            if (j == 0) possq = q.x * q.x + q.y * q.y + q.z * q.z + q.w * q.w;
        }
    }
    #pragma unroll
    for (int off = 8; off; off >>= 1) {
        part[0] += __shfl_down_sync(0xffffffffu, part[0], off, 16);
        part[1] += __shfl_down_sync(0xffffffffu, part[1], off, 16);
        part[2] += __shfl_down_sync(0xffffffffu, part[2], off, 16);
        part[3] += __shfl_down_sync(0xffffffffu, part[3], off, 16);
        possq   += __shfl_down_sync(0xffffffffu, possq,   off, 16);
    }

    float wloss = 0.0f;
    if (fl == 0) {
        #pragma unroll
        for (int k = 0; k < 4; k++) {
            int j = hw + (k << 4);
            if (valid[k]) {
                float bir = s_bi[j];
                float x = tp * part[k] + bir + b_u;
                float s = 1.0f / (1.0f + __expf(-x));
                if (j == 0) {
                    float e = 1.0f - s;
                    wloss += e * e + BATA * possq + LAMDA * bir * bir;
                } else {
                    wloss += s * s;
                }
            }
        }
    }
    wloss += __shfl_down_sync(0xffffffffu, wloss, 16);
    if (lane == 0) atomicAdd(&s_loss, wloss);

    if (tid == 0) atomicAdd(&s_loss, LAMDA * GAMA * b_u * b_u);
    __syncthreads();

    if (tid == 0) atomicAdd(out, s_loss);
}

extern "C" void kernel_launch(void* const* d_in, const int* in_sizes, int n_in,
                              void* d_out, int out_size)
{
    const float* bu          = (const float*)d_in[0];
    const float* bi          = (const float*)d_in[1];
    const float* qi          = (const float*)d_in[2];
    const float* pu          = (const float*)d_in[3];
    const float* uin         = (const float*)d_in[4];
    const int*   users       = (const int*)  d_in[5];
    const int*   pos_items   = (const int*)  d_in[6];
    const int*   neg_items   = (const int*)  d_in[7];
    const int*   hist_items  = (const int*)  d_in[8];
    const int*   hist_segids = (const int*)  d_in[9];

    const int B     = in_sizes[5];
    const int total = in_sizes[8];
    const int n_neg = in_sizes[7] / B;

    float* out = (float*)d_out;

    int* starts;
    cudaGetSymbolAddress((void**)&starts, g_starts);

    bounds_kernel<<<(total + 255) / 256, 256>>>(hist_segids, total, B, starts, out);

    cudaLaunchConfig_t cfg = {};
    cfg.gridDim  = dim3(B);
    cfg.blockDim = dim3(256);
    cfg.stream   = 0;
    cudaLaunchAttribute attr[1];
    attr[0].id = cudaLaunchAttributeProgrammaticStreamSerialization;
    attr[0].val.programmaticStreamSerializationAllowed = 1;
    cfg.attrs    = attr;
    cfg.numAttrs = 1;
    cudaLaunchKernelEx(&cfg, fism_kernel, bu, bi, qi, pu, uin, users,
                       pos_items, neg_items, n_neg, hist_items, out);
}